// round 6
// baseline (speedup 1.0000x reference)
#include <cuda_runtime.h>
#include <cuda_bf16.h>
#include <cuda_fp8.h>
#include <math.h>
#include <stdint.h>

#define NA     9216      // 96*96
#define CDIM   1280
#define HW48   2304      // 48*48
#define MT     72        // 9216/128 tiles per GEMM dim
#define NIT    20        // 1280/64 K-iterations (BK=64 fp8)
#define SSPLIT 64
#define SROWB  80        // smem row stride in BYTES (64B data + 16B skew)

// ---------------- scratch (device globals; no allocation allowed) ----------
__device__ float g_tmp[2][CDIM * 64 * 96];           // horizontal-resize temps
__device__ unsigned char g_refb[(size_t)NA * CDIM];  // (N, C) row-major e4m3
__device__ unsigned char g_featb[(size_t)NA * CDIM];
__device__ __nv_bfloat16 g_E[(size_t)NA * NA];       // exp(sim), bf16, 170MB
__device__ float g_Zpart[MT * NA];
__device__ float g_invZ[NA];
__device__ float g_partial[SSPLIT * NA];
__device__ float g_x1[HW48];
__device__ float g_out48[HW48];
__device__ int   g_active[NA];
__device__ int   g_count;
__device__ unsigned char g_flag[NA];
__device__ int4   g_it4[96];
__device__ float4 g_wt4[96];

// ---------------- PTX helpers (baseline features only) ---------------------
__device__ __forceinline__ uint32_t smem_u32(const void* p) {
    uint32_t a;
    asm("{ .reg .u64 t; cvta.to.shared.u64 t, %1; cvt.u32.u64 %0, t; }"
        : "=r"(a) : "l"(p));
    return a;
}
__device__ __forceinline__ void cpa16(uint32_t dst, const void* src, int sz) {
    asm volatile("cp.async.cg.shared.global [%0], [%1], 16, %2;"
                 :: "r"(dst), "l"(src), "r"(sz) : "memory");
}
#define CP_COMMIT() asm volatile("cp.async.commit_group;" ::: "memory")
#define CP_WAIT(n)  asm volatile("cp.async.wait_group %0;" :: "n"(n) : "memory")

__device__ __forceinline__ void ldsm4(uint32_t* r, uint32_t addr) {
    asm volatile("ldmatrix.sync.aligned.m8n8.x4.shared.b16 {%0,%1,%2,%3}, [%4];"
                 : "=r"(r[0]), "=r"(r[1]), "=r"(r[2]), "=r"(r[3]) : "r"(addr));
}
// fp8 e4m3 MMA: D(f32) += A(16x32 e4m3) * B(32x8 e4m3)
__device__ __forceinline__ void mma16832(float* d, const uint32_t* a,
                                         const uint32_t* b) {
    asm volatile(
        "mma.sync.aligned.m16n8k32.row.col.f32.e4m3.e4m3.f32 "
        "{%0,%1,%2,%3},{%4,%5,%6,%7},{%8,%9},{%0,%1,%2,%3};"
        : "+f"(d[0]), "+f"(d[1]), "+f"(d[2]), "+f"(d[3])
        : "r"(a[0]), "r"(a[1]), "r"(a[2]), "r"(a[3]), "r"(b[0]), "r"(b[1]));
}

// packed f32x2 (base sm_100+ PTX feature)
typedef unsigned long long ull;
__device__ __forceinline__ ull pk2(float lo, float hi) {
    ull r; asm("mov.b64 %0, {%1,%2};" : "=l"(r) : "f"(lo), "f"(hi)); return r;
}
__device__ __forceinline__ void upk2(float& lo, float& hi, ull v) {
    asm("mov.b64 {%0,%1}, %2;" : "=f"(lo), "=f"(hi) : "l"(v));
}
__device__ __forceinline__ ull fma2(ull a, ull b, ull c) {
    ull r; asm("fma.rn.f32x2 %0, %1, %2, %3;" : "=l"(r) : "l"(a), "l"(b), "l"(c));
    return r;
}
__device__ __forceinline__ ull mul2(ull a, ull b) {
    ull r; asm("mul.rn.f32x2 %0, %1, %2;" : "=l"(r) : "l"(a), "l"(b)); return r;
}
__device__ __forceinline__ ull add2(ull a, ull b) {
    ull r; asm("add.rn.f32x2 %0, %1, %2;" : "=l"(r) : "l"(a), "l"(b)); return r;
}

// ---------------- mask + compaction ----------------------------------------
__global__ void k_flag(const float* __restrict__ guid) {
    int i = blockIdx.x * blockDim.x + threadIdx.x;
    if (i >= NA) return;
    int by = i / 96, bx = i % 96;
    const float* p = guid + (by * 8) * 768 + bx * 8;
    bool all = true;
    #pragma unroll
    for (int dy = 0; dy < 8; dy++)
        #pragma unroll
        for (int dx = 0; dx < 8; dx++)
            all = all && (p[dy * 768 + dx] > 0.5f);
    g_flag[i] = all ? 1 : 0;
}

__global__ void k_compact() {
    __shared__ int s_cnt[256];
    __shared__ int s_off[256];
    int t = threadIdx.x;
    int c = 0;
    for (int k = 0; k < 36; k++) c += g_flag[t * 36 + k];
    s_cnt[t] = c;
    __syncthreads();
    if (t == 0) {
        int acc = 0;
        for (int i = 0; i < 256; i++) { s_off[i] = acc; acc += s_cnt[i]; }
        g_count = acc;
    }
    __syncthreads();
    int off = s_off[t];
    for (int k = 0; k < 36; k++) {
        int i = t * 36 + k;
        if (g_flag[i]) g_active[off++] = i;
    }
}

// ---------------- cubic weight tables ---------------------------------------
__device__ __forceinline__ float keys_cubic(float x) {
    x = fabsf(x);
    if (x < 1.f)  return ((1.5f * x - 2.5f) * x) * x + 1.f;
    if (x < 2.f)  return ((-0.5f * x + 2.5f) * x - 4.f) * x + 2.f;
    return 0.f;
}

__global__ void k_weights() {
    int o = threadIdx.x;
    if (o >= 96) return;
    float s = (o + 0.5f) * (64.f / 96.f) - 0.5f;
    int fl = (int)floorf(s);
    int idx[4]; float w[4]; float tot = 0.f;
    #pragma unroll
    for (int t = 0; t < 4; t++) {
        int ii = fl - 1 + t;
        float ww = (ii >= 0 && ii < 64) ? keys_cubic(s - (float)ii) : 0.f;
        idx[t] = min(max(ii, 0), 63);
        w[t] = ww;
        tot += ww;
    }
    float inv = 1.f / tot;
    g_it4[o] = make_int4(idx[0], idx[1], idx[2], idx[3]);
    g_wt4[o] = make_float4(w[0]*inv, w[1]*inv, w[2]*inv, w[3]*inv);
}

// horizontal cubic for both tensors: z=0 ft_cor, z=1 ref
__global__ void k_resize_h2(const float* __restrict__ in0,
                            const float* __restrict__ in1) {
    int idx = blockIdx.x * blockDim.x + threadIdx.x;
    if (idx >= CDIM * 64 * 96) return;
    const float* in = blockIdx.z ? in1 : in0;
    int xo = idx % 96;
    int r  = idx / 96;
    int4  ti = g_it4[xo];
    float4 w = g_wt4[xo];
    const float* p = in + r * 64;
    g_tmp[blockIdx.z][idx] = w.x*p[ti.x] + w.y*p[ti.y] + w.z*p[ti.z] + w.w*p[ti.w];
}

// vertical cubic + transpose to (N, C) e4m3; z=0 -> feat, z=1 -> ref
__global__ void k_resize_vt2() {
    __shared__ float t[32][33];
    int z = blockIdx.z;
    int n = blockIdx.x * 32 + threadIdx.x;
    int yo = n / 96, xo = n % 96;
    int4  ti = g_it4[yo];
    float4 w = g_wt4[yo];
    const float* base = g_tmp[z];
    #pragma unroll
    for (int i = 0; i < 4; i++) {
        int c = blockIdx.y * 32 + threadIdx.y + i * 8;
        const float* p = base + c * (64 * 96) + xo;
        t[threadIdx.y + i * 8][threadIdx.x] =
            w.x*p[ti.x*96] + w.y*p[ti.y*96] + w.z*p[ti.z*96] + w.w*p[ti.w*96];
    }
    __syncthreads();
    unsigned char* dst = z ? g_refb : g_featb;
    #pragma unroll
    for (int i = 0; i < 4; i++) {
        int nn = blockIdx.x * 32 + threadIdx.y + i * 8;
        float v = t[threadIdx.x][threadIdx.y + i * 8];
        dst[(size_t)nn * CDIM + blockIdx.y * 32 + threadIdx.x] =
            __nv_cvt_float_to_fp8(v, __NV_SATFINITE, __NV_E4M3);
    }
}

// ---------------- e4m3 mma.sync GEMM + poly-exp + row sums ------------------
// C[128x128] tile: 8 warps (4m x 2n). BK=64 fp8, 3-stage cp.async pipeline.
__global__ __launch_bounds__(256, 2) void k_gemm() {
    int count = g_count;
    int m0 = blockIdx.y * 128;
    if (m0 >= count) return;
    int n0 = blockIdx.x * 128;

    extern __shared__ __align__(16) char dyn[];
    char* sA = dyn;                                  // 3 stages x 128*SROWB
    char* sB = dyn + 3 * 128 * SROWB;
    __shared__ int   s_act[128];
    __shared__ float s_rows[2][128];

    int tid = threadIdx.x, lane = tid & 31, wid = tid >> 5;
    int wm = wid & 3, wn = wid >> 2;

    if (tid < 128)
        s_act[tid] = (m0 + tid < count) ? g_active[m0 + tid] : -1;
    __syncthreads();

    // per-thread load coords: 2 rows each for A and B, 16B per cp.async
    int row0 = tid >> 2,         c0 = tid & 3;          // 16B unit in 64B
    int row1 = (tid + 256) >> 2, c1 = (tid + 256) & 3;
    int ga0 = s_act[row0], ga1 = s_act[row1];
    const unsigned char* a0 = g_refb + (size_t)max(ga0, 0) * CDIM + c0 * 16;
    const unsigned char* a1 = g_refb + (size_t)max(ga1, 0) * CDIM + c1 * 16;
    const unsigned char* b0 = g_featb + (size_t)(n0 + row0) * CDIM + c0 * 16;
    const unsigned char* b1 = g_featb + (size_t)(n0 + row1) * CDIM + c1 * 16;
    uint32_t so0 = (uint32_t)(row0 * SROWB + c0 * 16);
    uint32_t so1 = (uint32_t)(row1 * SROWB + c1 * 16);

    auto issue = [&](int it, int stg) {
        int k0 = it * 64;
        uint32_t aB = smem_u32(sA + stg * 128 * SROWB);
        uint32_t bB = smem_u32(sB + stg * 128 * SROWB);
        cpa16(aB + so0, a0 + k0, ga0 >= 0 ? 16 : 0);
        cpa16(bB + so0, b0 + k0, 16);
        cpa16(aB + so1, a1 + k0, ga1 >= 0 ? 16 : 0);
        cpa16(bB + so1, b1 + k0, 16);
    };

    issue(0, 0); CP_COMMIT();
    issue(1, 1); CP_COMMIT();

    float d[2][8][4] = {};

    for (int it = 0; it < NIT; it++) {
        int stg = it - (it / 3) * 3;
        if (it < NIT - 1) CP_WAIT(1); else CP_WAIT(0);
        __syncthreads();

        if (it + 2 < NIT) {
            int ns = (it + 2) - ((it + 2) / 3) * 3;
            issue(it + 2, ns);
            CP_COMMIT();
        }

        uint32_t aBase = smem_u32(sA + stg * 128 * SROWB);
        uint32_t bBase = smem_u32(sB + stg * 128 * SROWB);
        #pragma unroll
        for (int s = 0; s < 2; s++) {            // two k32 steps per BK=64
            uint32_t a[2][4];
            #pragma unroll
            for (int sub = 0; sub < 2; sub++) {
                int row = wm * 32 + sub * 16 + (lane & 7) + ((lane >> 3) & 1) * 8;
                int kb  = s * 32 + ((lane >> 4) & 1) * 16;   // byte offset
                ldsm4(a[sub], aBase + (uint32_t)(row * SROWB + kb));
            }
            uint32_t b[4][4];
            #pragma unroll
            for (int bt = 0; bt < 4; bt++) {
                int grp = lane >> 3;
                int row = wn * 64 + bt * 16 + (grp >> 1) * 8 + (lane & 7);
                int kb  = s * 32 + (grp & 1) * 16;
                ldsm4(b[bt], bBase + (uint32_t)(row * SROWB + kb));
            }
            #pragma unroll
            for (int sub = 0; sub < 2; sub++)
                #pragma unroll
                for (int nt = 0; nt < 8; nt++)
                    mma16832(d[sub][nt], a[sub], &b[nt >> 1][(nt & 1) * 2]);
        }
    }

    // --- epilogue: packed f32x2 order-4 poly exp, bf16 E, row sums ----------
    const ull SC  = pk2(1e-3f, 1e-3f);
    const ull C24 = pk2(1.f/24.f, 1.f/24.f);
    const ull C6  = pk2(1.f/6.f, 1.f/6.f);
    const ull CH  = pk2(0.5f, 0.5f);
    const ull C1  = pk2(1.f, 1.f);

    int g  = lane >> 2;
    int lc = lane & 3;
    #pragma unroll
    for (int sub = 0; sub < 2; sub++) {
        int rA = m0 + wm * 32 + sub * 16 + g;
        int rB = rA + 8;
        bool vA = (rA < count), vB = (rB < count);
        ull rsA = 0ull, rsB = 0ull;
        #pragma unroll
        for (int nt = 0; nt < 8; nt++) {
            int col = n0 + wn * 64 + nt * 8 + lc * 2;
            ull xA = mul2(pk2(d[sub][nt][0], d[sub][nt][1]), SC);
            ull tA = fma2(xA, C24, C6);
            tA = fma2(xA, tA, CH);
            tA = fma2(xA, tA, C1);
            ull eA = fma2(xA, tA, C1);
            rsA = add2(rsA, eA);
            ull xB = mul2(pk2(d[sub][nt][2], d[sub][nt][3]), SC);
            ull tB = fma2(xB, C24, C6);
            tB = fma2(xB, tB, CH);
            tB = fma2(xB, tB, C1);
            ull eB = fma2(xB, tB, C1);
            rsB = add2(rsB, eB);
            if (vA) {
                float e0, e1; upk2(e0, e1, eA);
                __nv_bfloat162 p = __floats2bfloat162_rn(e0, e1);
                *(uint32_t*)(g_E + (size_t)rA * NA + col) = *(uint32_t*)&p;
            }
            if (vB) {
                float e2, e3; upk2(e2, e3, eB);
                __nv_bfloat162 p = __floats2bfloat162_rn(e2, e3);
                *(uint32_t*)(g_E + (size_t)rB * NA + col) = *(uint32_t*)&p;
            }
        }
        float a0f, a1f, b0f, b1f;
        upk2(a0f, a1f, rsA);
        upk2(b0f, b1f, rsB);
        float sA2 = a0f + a1f, sB2 = b0f + b1f;
        sA2 += __shfl_xor_sync(0xffffffffu, sA2, 1);
        sA2 += __shfl_xor_sync(0xffffffffu, sA2, 2);
        sB2 += __shfl_xor_sync(0xffffffffu, sB2, 1);
        sB2 += __shfl_xor_sync(0xffffffffu, sB2, 2);
        if (lc == 0) {
            s_rows[wn][wm * 32 + sub * 16 + g]     = sA2;
            s_rows[wn][wm * 32 + sub * 16 + g + 8] = sB2;
        }
    }
    __syncthreads();
    if (tid < 128) {
        int m = m0 + tid;
        if (m < count)
            g_Zpart[blockIdx.x * NA + m] = s_rows[0][tid] + s_rows[1][tid];
    }
}

__global__ void k_invz() {
    int i = blockIdx.x * blockDim.x + threadIdx.x;
    if (i >= NA || i >= g_count) return;
    float z = 0.f;
    for (int t = 0; t < MT; t++) z += g_Zpart[t * NA + i];
    g_invZ[i] = 1.f / z;
}

// ---------------- column reduction: attn_out_j = sum_i E[i,j]/Z_i ----------
__global__ void k_colreduce() {
    int jj = blockIdx.x * 256 + threadIdx.x;   // bf16x2 pair index
    int s  = blockIdx.y;
    int count = g_count;
    float a0 = 0.f, a1 = 0.f;
    for (int ci = s; ci < count; ci += SSPLIT) {
        __nv_bfloat162 v = ((const __nv_bfloat162*)(g_E + (size_t)ci * NA))[jj];
        float iz = g_invZ[ci];
        a0 += __low2float(v) * iz;
        a1 += __high2float(v) * iz;
    }
    g_partial[s * NA + 2 * jj]     = a0;
    g_partial[s * NA + 2 * jj + 1] = a1;
}

__global__ void k_colfinish(float* __restrict__ maskout) {
    int j = blockIdx.x * blockDim.x + threadIdx.x;
    if (j >= NA) return;
    float a = 0.f;
    for (int s = 0; s < SSPLIT; s++) a += g_partial[s * NA + j];
    maskout[j] = a;
}

// ---------------- bilinear align_corners 96 -> 48 ---------------------------
__global__ void k_x1(const float* __restrict__ mask) {
    int k = blockIdx.x * blockDim.x + threadIdx.x;
    if (k >= HW48) return;
    int yo = k / 48, xo = k % 48;
    const float step = 95.f / 47.f;
    float ys = yo * step, xs = xo * step;
    int y0 = (int)floorf(ys), x0 = (int)floorf(xs);
    int y1 = min(y0 + 1, 95), x1i = min(x0 + 1, 95);
    float wy = ys - (float)y0, wx = xs - (float)x0;
    float a = mask[y0 * 96 + x0],  b = mask[y0 * 96 + x1i];
    float c = mask[y1 * 96 + x0],  d = mask[y1 * 96 + x1i];
    g_x1[k] = (a * (1.f - wx) + b * wx) * (1.f - wy) + (c * (1.f - wx) + d * wx) * wy;
}

__global__ void k_attn(const float* __restrict__ A) {
    __shared__ float red[256];
    int j = blockIdx.x;
    int t = threadIdx.x;
    float acc = 0.f;
    const float* row = A + (size_t)j * HW48;
    for (int k = t; k < HW48; k += 256) acc += g_x1[k] * row[k];
    red[t] = acc;
    __syncthreads();
    for (int s = 128; s; s >>= 1) {
        if (t < s) red[t] += red[t + s];
        __syncthreads();
    }
    if (t == 0) g_out48[j] = red[0];
}

__global__ void k_trimap(float* __restrict__ out) {
    int idx = blockIdx.x * blockDim.x + threadIdx.x;
    if (idx >= 768 * 768) return;
    int ox = idx % 768, oy = idx / 768;
    float sx = (ox + 0.5f) * (1.f / 16.f) - 0.5f;
    float sy = (oy + 0.5f) * (1.f / 16.f) - 0.5f;
    int x0 = (int)floorf(sx), y0 = (int)floorf(sy);
    float wx = sx - (float)x0, wy = sy - (float)y0;
    int x0c = max(x0, 0), x1c = min(x0 + 1, 47);
    int y0c = max(y0, 0), y1c = min(y0 + 1, 47);
    float a = g_out48[y0c * 48 + x0c], b = g_out48[y0c * 48 + x1c];
    float c = g_out48[y1c * 48 + x0c], d = g_out48[y1c * 48 + x1c];
    out[idx] = (a * (1.f - wx) + b * wx) * (1.f - wy) + (c * (1.f - wx) + d * wx) * wy;
}

// ---------------- launch ----------------------------------------------------
extern "C" void kernel_launch(void* const* d_in, const int* in_sizes, int n_in,
                              void* d_out, int out_size) {
    (void)in_sizes; (void)n_in; (void)out_size;
    const float* ref_img = (const float*)d_in[0];
    const float* ft_cor  = (const float*)d_in[1];
    const float* attnA   = (const float*)d_in[2];
    const float* ft_mat  = (const float*)d_in[3];
    const float* guid    = (const float*)d_in[4];

    float* out     = (float*)d_out;
    float* trimap  = out;                       // 768*768
    float* matting = out + 768 * 768;           // 1280*64*64
    float* maskout = matting + 1280 * 64 * 64;  // 9216

    k_flag<<<36, 256>>>(guid);
    k_compact<<<1, 256>>>();
    k_weights<<<1, 96>>>();

    int nrh = (CDIM * 64 * 96 + 255) / 256;
    k_resize_h2<<<dim3(nrh, 1, 2), 256>>>(ft_cor, ref_img);
    k_resize_vt2<<<dim3(NA / 32, CDIM / 32, 2), dim3(32, 8)>>>();

    const int GEMM_SMEM = 3 * 128 * SROWB * 2;   // 61440
    cudaFuncSetAttribute(k_gemm, cudaFuncAttributeMaxDynamicSharedMemorySize,
                         GEMM_SMEM);
    k_gemm<<<dim3(MT, MT), 256, GEMM_SMEM>>>();

    k_invz<<<36, 256>>>();
    k_colreduce<<<dim3(18, SSPLIT), 256>>>();
    k_colfinish<<<36, 256>>>(maskout);

    k_x1<<<9, 256>>>(maskout);
    k_attn<<<HW48, 256>>>(attnA);
    k_trimap<<<(768 * 768 + 255) / 256, 256>>>(trimap);

    cudaMemcpyAsync(matting, ft_mat, (size_t)1280 * 64 * 64 * sizeof(float),
                    cudaMemcpyDeviceToDevice);
}

// round 7
// speedup vs baseline: 1.0289x; 1.0289x over previous
#include <cuda_runtime.h>
#include <cuda_bf16.h>
#include <cuda_fp8.h>
#include <math.h>
#include <stdint.h>

#define NA     9216      // 96*96
#define CDIM   1280
#define HW48   2304      // 48*48
#define MT     72        // 9216/128 tiles per GEMM dim
#define NIT    20        // 1280/64 K-iterations (BK=64 fp8)
#define SSPLIT 64
#define SROWB  80        // smem row stride in BYTES (64B data + 16B skew)

// ---------------- scratch (device globals; no allocation allowed) ----------
__device__ float g_tmp[2][CDIM * 64 * 96];           // horizontal-resize temps
__device__ unsigned char g_refb[(size_t)NA * CDIM];  // (N, C) row-major e4m3
__device__ unsigned char g_featb[(size_t)NA * CDIM];
__device__ __nv_bfloat16 g_E[(size_t)NA * NA];       // exp(sim), bf16, 170MB
__device__ float g_Zpart[MT * NA];
__device__ float g_invZ[NA];
__device__ float g_partial[SSPLIT * NA];
__device__ float g_x1[HW48];
__device__ float g_out48[HW48];
__device__ int   g_active[NA];
__device__ int   g_count;
__device__ unsigned char g_flag[NA];
__device__ int4   g_it4[96];
__device__ float4 g_wt4[96];

// ---------------- PTX helpers (baseline features only) ---------------------
__device__ __forceinline__ uint32_t smem_u32(const void* p) {
    uint32_t a;
    asm("{ .reg .u64 t; cvta.to.shared.u64 t, %1; cvt.u32.u64 %0, t; }"
        : "=r"(a) : "l"(p));
    return a;
}
__device__ __forceinline__ void cpa16(uint32_t dst, const void* src, int sz) {
    asm volatile("cp.async.cg.shared.global [%0], [%1], 16, %2;"
                 :: "r"(dst), "l"(src), "r"(sz) : "memory");
}
#define CP_COMMIT() asm volatile("cp.async.commit_group;" ::: "memory")
#define CP_WAIT(n)  asm volatile("cp.async.wait_group %0;" :: "n"(n) : "memory")

__device__ __forceinline__ void ldsm4(uint32_t* r, uint32_t addr) {
    asm volatile("ldmatrix.sync.aligned.m8n8.x4.shared.b16 {%0,%1,%2,%3}, [%4];"
                 : "=r"(r[0]), "=r"(r[1]), "=r"(r[2]), "=r"(r[3]) : "r"(addr));
}
// fp8 e4m3 MMA: D(f32) += A(16x32 e4m3) * B(32x8 e4m3)
__device__ __forceinline__ void mma16832(float* d, const uint32_t* a,
                                         const uint32_t* b) {
    asm volatile(
        "mma.sync.aligned.m16n8k32.row.col.f32.e4m3.e4m3.f32 "
        "{%0,%1,%2,%3},{%4,%5,%6,%7},{%8,%9},{%0,%1,%2,%3};"
        : "+f"(d[0]), "+f"(d[1]), "+f"(d[2]), "+f"(d[3])
        : "r"(a[0]), "r"(a[1]), "r"(a[2]), "r"(a[3]), "r"(b[0]), "r"(b[1]));
}

// packed f32x2 (base sm_100+ PTX feature)
typedef unsigned long long ull;
__device__ __forceinline__ ull pk2(float lo, float hi) {
    ull r; asm("mov.b64 %0, {%1,%2};" : "=l"(r) : "f"(lo), "f"(hi)); return r;
}
__device__ __forceinline__ void upk2(float& lo, float& hi, ull v) {
    asm("mov.b64 {%0,%1}, %2;" : "=f"(lo), "=f"(hi) : "l"(v));
}
__device__ __forceinline__ ull fma2(ull a, ull b, ull c) {
    ull r; asm("fma.rn.f32x2 %0, %1, %2, %3;" : "=l"(r) : "l"(a), "l"(b), "l"(c));
    return r;
}
__device__ __forceinline__ ull add2(ull a, ull b) {
    ull r; asm("add.rn.f32x2 %0, %1, %2;" : "=l"(r) : "l"(a), "l"(b)); return r;
}

// ---------------- mask + compaction ----------------------------------------
__global__ void k_flag(const float* __restrict__ guid) {
    int i = blockIdx.x * blockDim.x + threadIdx.x;
    if (i >= NA) return;
    int by = i / 96, bx = i % 96;
    const float* p = guid + (by * 8) * 768 + bx * 8;
    bool all = true;
    #pragma unroll
    for (int dy = 0; dy < 8; dy++)
        #pragma unroll
        for (int dx = 0; dx < 8; dx++)
            all = all && (p[dy * 768 + dx] > 0.5f);
    g_flag[i] = all ? 1 : 0;
}

__global__ void k_compact() {
    __shared__ int s_cnt[256];
    __shared__ int s_off[256];
    int t = threadIdx.x;
    int c = 0;
    for (int k = 0; k < 36; k++) c += g_flag[t * 36 + k];
    s_cnt[t] = c;
    __syncthreads();
    if (t == 0) {
        int acc = 0;
        for (int i = 0; i < 256; i++) { s_off[i] = acc; acc += s_cnt[i]; }
        g_count = acc;
    }
    __syncthreads();
    int off = s_off[t];
    for (int k = 0; k < 36; k++) {
        int i = t * 36 + k;
        if (g_flag[i]) g_active[off++] = i;
    }
}

// ---------------- cubic weight tables ---------------------------------------
__device__ __forceinline__ float keys_cubic(float x) {
    x = fabsf(x);
    if (x < 1.f)  return ((1.5f * x - 2.5f) * x) * x + 1.f;
    if (x < 2.f)  return ((-0.5f * x + 2.5f) * x - 4.f) * x + 2.f;
    return 0.f;
}

__global__ void k_weights() {
    int o = threadIdx.x;
    if (o >= 96) return;
    float s = (o + 0.5f) * (64.f / 96.f) - 0.5f;
    int fl = (int)floorf(s);
    int idx[4]; float w[4]; float tot = 0.f;
    #pragma unroll
    for (int t = 0; t < 4; t++) {
        int ii = fl - 1 + t;
        float ww = (ii >= 0 && ii < 64) ? keys_cubic(s - (float)ii) : 0.f;
        idx[t] = min(max(ii, 0), 63);
        w[t] = ww;
        tot += ww;
    }
    float inv = 1.f / tot;
    g_it4[o] = make_int4(idx[0], idx[1], idx[2], idx[3]);
    g_wt4[o] = make_float4(w[0]*inv, w[1]*inv, w[2]*inv, w[3]*inv);
}

// horizontal cubic, smem-staged: 16 rows/block; z=0 ft_cor, z=1 ref
__global__ __launch_bounds__(256) void k_resize_h2(const float* __restrict__ in0,
                                                   const float* __restrict__ in1) {
    __shared__ float rowbuf[16][64];
    const float* in = blockIdx.z ? in1 : in0;
    int tid = threadIdx.x;
    int base = blockIdx.x * 16;             // first input row of this block

    #pragma unroll
    for (int k = 0; k < 4; k++) {
        int idx = tid + k * 256;            // 0..1023
        rowbuf[idx >> 6][idx & 63] = in[(size_t)base * 64 + idx];
    }
    __syncthreads();

    float* outp = g_tmp[blockIdx.z] + (size_t)base * 96;
    #pragma unroll
    for (int k = 0; k < 6; k++) {
        int idx = tid + k * 256;            // 0..1535
        int row = idx / 96, xo = idx - row * 96;
        int4  ti = g_it4[xo];
        float4 w = g_wt4[xo];
        const float* p = rowbuf[row];
        outp[idx] = w.x*p[ti.x] + w.y*p[ti.y] + w.z*p[ti.z] + w.w*p[ti.w];
    }
}

// vertical cubic + transpose to (N, C) e4m3; z=0 -> feat, z=1 -> ref
__global__ void k_resize_vt2() {
    __shared__ float t[32][33];
    int z = blockIdx.z;
    int n = blockIdx.x * 32 + threadIdx.x;
    int yo = n / 96, xo = n % 96;
    int4  ti = g_it4[yo];
    float4 w = g_wt4[yo];
    const float* base = g_tmp[z];
    #pragma unroll
    for (int i = 0; i < 4; i++) {
        int c = blockIdx.y * 32 + threadIdx.y + i * 8;
        const float* p = base + c * (64 * 96) + xo;
        t[threadIdx.y + i * 8][threadIdx.x] =
            w.x*p[ti.x*96] + w.y*p[ti.y*96] + w.z*p[ti.z*96] + w.w*p[ti.w*96];
    }
    __syncthreads();
    unsigned char* dst = z ? g_refb : g_featb;
    #pragma unroll
    for (int i = 0; i < 4; i++) {
        int nn = blockIdx.x * 32 + threadIdx.y + i * 8;
        float v = t[threadIdx.x][threadIdx.y + i * 8];
        dst[(size_t)nn * CDIM + blockIdx.y * 32 + threadIdx.x] =
            __nv_cvt_float_to_fp8(v, __NV_SATFINITE, __NV_E4M3);
    }
}

// ---------------- e4m3 mma.sync GEMM + folded poly-exp + row sums -----------
// C[128x128] tile: 8 warps (4m x 2n). BK=64 fp8, 3-stage cp.async pipeline.
__global__ __launch_bounds__(256, 2) void k_gemm() {
    int count = g_count;
    int m0 = blockIdx.y * 128;
    if (m0 >= count) return;
    int n0 = blockIdx.x * 128;

    extern __shared__ __align__(16) char dyn[];
    char* sA = dyn;                                  // 3 stages x 128*SROWB
    char* sB = dyn + 3 * 128 * SROWB;
    __shared__ int   s_act[128];
    __shared__ float s_rows[2][128];

    int tid = threadIdx.x, lane = tid & 31, wid = tid >> 5;
    int wm = wid & 3, wn = wid >> 2;

    if (tid < 128)
        s_act[tid] = (m0 + tid < count) ? g_active[m0 + tid] : -1;
    __syncthreads();

    // per-thread load coords: 2 rows each for A and B, 16B per cp.async
    int row0 = tid >> 2,         c0 = tid & 3;          // 16B unit in 64B
    int row1 = (tid + 256) >> 2, c1 = (tid + 256) & 3;
    int ga0 = s_act[row0], ga1 = s_act[row1];
    const unsigned char* a0 = g_refb + (size_t)max(ga0, 0) * CDIM + c0 * 16;
    const unsigned char* a1 = g_refb + (size_t)max(ga1, 0) * CDIM + c1 * 16;
    const unsigned char* b0 = g_featb + (size_t)(n0 + row0) * CDIM + c0 * 16;
    const unsigned char* b1 = g_featb + (size_t)(n0 + row1) * CDIM + c1 * 16;
    uint32_t so0 = (uint32_t)(row0 * SROWB + c0 * 16);
    uint32_t so1 = (uint32_t)(row1 * SROWB + c1 * 16);

    auto issue = [&](int it, int stg) {
        int k0 = it * 64;
        uint32_t aB = smem_u32(sA + stg * 128 * SROWB);
        uint32_t bB = smem_u32(sB + stg * 128 * SROWB);
        cpa16(aB + so0, a0 + k0, ga0 >= 0 ? 16 : 0);
        cpa16(bB + so0, b0 + k0, 16);
        cpa16(aB + so1, a1 + k0, ga1 >= 0 ? 16 : 0);
        cpa16(bB + so1, b1 + k0, 16);
    };

    issue(0, 0); CP_COMMIT();
    issue(1, 1); CP_COMMIT();

    float d[2][8][4] = {};

    for (int it = 0; it < NIT; it++) {
        int stg = it - (it / 3) * 3;
        if (it < NIT - 1) CP_WAIT(1); else CP_WAIT(0);
        __syncthreads();

        if (it + 2 < NIT) {
            int ns = (it + 2) - ((it + 2) / 3) * 3;
            issue(it + 2, ns);
            CP_COMMIT();
        }

        uint32_t aBase = smem_u32(sA + stg * 128 * SROWB);
        uint32_t bBase = smem_u32(sB + stg * 128 * SROWB);
        #pragma unroll
        for (int s = 0; s < 2; s++) {            // two k32 steps per BK=64
            uint32_t a[2][4];
            #pragma unroll
            for (int sub = 0; sub < 2; sub++) {
                int row = wm * 32 + sub * 16 + (lane & 7) + ((lane >> 3) & 1) * 8;
                int kb  = s * 32 + ((lane >> 4) & 1) * 16;   // byte offset
                ldsm4(a[sub], aBase + (uint32_t)(row * SROWB + kb));
            }
            uint32_t b[4][4];
            #pragma unroll
            for (int bt = 0; bt < 4; bt++) {
                int grp = lane >> 3;
                int row = wn * 64 + bt * 16 + (grp >> 1) * 8 + (lane & 7);
                int kb  = s * 32 + (grp & 1) * 16;
                ldsm4(b[bt], bBase + (uint32_t)(row * SROWB + kb));
            }
            #pragma unroll
            for (int sub = 0; sub < 2; sub++)
                #pragma unroll
                for (int nt = 0; nt < 8; nt++)
                    mma16832(d[sub][nt], a[sub], &b[nt >> 1][(nt & 1) * 2]);
        }
    }

    // --- epilogue: exp(s/1000) via order-3 poly with FOLDED scale ----------
    //     exp(c*s) = 1 + s*(c + s*(c^2/2 + s*c^3/6)); 3 fma2 + 1 add2 / 2 vals
    const ull A3 = pk2(1.6666667e-10f, 1.6666667e-10f);   // c^3/6
    const ull A2 = pk2(5.0e-7f,        5.0e-7f);          // c^2/2
    const ull A1 = pk2(1.0e-3f,        1.0e-3f);          // c
    const ull C1 = pk2(1.f, 1.f);

    int g  = lane >> 2;
    int lc = lane & 3;
    #pragma unroll
    for (int sub = 0; sub < 2; sub++) {
        int rA = m0 + wm * 32 + sub * 16 + g;
        int rB = rA + 8;
        bool vA = (rA < count), vB = (rB < count);
        ull rsA = 0ull, rsB = 0ull;
        #pragma unroll
        for (int nt = 0; nt < 8; nt++) {
            int col = n0 + wn * 64 + nt * 8 + lc * 2;
            ull sAp = pk2(d[sub][nt][0], d[sub][nt][1]);
            ull tA = fma2(sAp, A3, A2);
            tA = fma2(sAp, tA, A1);
            ull eA = fma2(sAp, tA, C1);
            rsA = add2(rsA, eA);
            ull sBp = pk2(d[sub][nt][2], d[sub][nt][3]);
            ull tB = fma2(sBp, A3, A2);
            tB = fma2(sBp, tB, A1);
            ull eB = fma2(sBp, tB, C1);
            rsB = add2(rsB, eB);
            if (vA) {
                float e0, e1; upk2(e0, e1, eA);
                __nv_bfloat162 p = __floats2bfloat162_rn(e0, e1);
                *(uint32_t*)(g_E + (size_t)rA * NA + col) = *(uint32_t*)&p;
            }
            if (vB) {
                float e2, e3; upk2(e2, e3, eB);
                __nv_bfloat162 p = __floats2bfloat162_rn(e2, e3);
                *(uint32_t*)(g_E + (size_t)rB * NA + col) = *(uint32_t*)&p;
            }
        }
        float a0f, a1f, b0f, b1f;
        upk2(a0f, a1f, rsA);
        upk2(b0f, b1f, rsB);
        float sA2 = a0f + a1f, sB2 = b0f + b1f;
        sA2 += __shfl_xor_sync(0xffffffffu, sA2, 1);
        sA2 += __shfl_xor_sync(0xffffffffu, sA2, 2);
        sB2 += __shfl_xor_sync(0xffffffffu, sB2, 1);
        sB2 += __shfl_xor_sync(0xffffffffu, sB2, 2);
        if (lc == 0) {
            s_rows[wn][wm * 32 + sub * 16 + g]     = sA2;
            s_rows[wn][wm * 32 + sub * 16 + g + 8] = sB2;
        }
    }
    __syncthreads();
    if (tid < 128) {
        int m = m0 + tid;
        if (m < count)
            g_Zpart[blockIdx.x * NA + m] = s_rows[0][tid] + s_rows[1][tid];
    }
}

__global__ void k_invz() {
    int i = blockIdx.x * blockDim.x + threadIdx.x;
    if (i >= NA || i >= g_count) return;
    float z = 0.f;
    for (int t = 0; t < MT; t++) z += g_Zpart[t * NA + i];
    g_invZ[i] = 1.f / z;
}

// ---------------- column reduction: attn_out_j = sum_i E[i,j]/Z_i ----------
__global__ void k_colreduce() {
    int jj = blockIdx.x * 256 + threadIdx.x;   // bf16x2 pair index
    int s  = blockIdx.y;
    int count = g_count;
    float a0 = 0.f, a1 = 0.f;
    for (int ci = s; ci < count; ci += SSPLIT) {
        __nv_bfloat162 v = ((const __nv_bfloat162*)(g_E + (size_t)ci * NA))[jj];
        float iz = g_invZ[ci];
        a0 += __low2float(v) * iz;
        a1 += __high2float(v) * iz;
    }
    g_partial[s * NA + 2 * jj]     = a0;
    g_partial[s * NA + 2 * jj + 1] = a1;
}

__global__ void k_colfinish(float* __restrict__ maskout) {
    int j = blockIdx.x * blockDim.x + threadIdx.x;
    if (j >= NA) return;
    float a = 0.f;
    for (int s = 0; s < SSPLIT; s++) a += g_partial[s * NA + j];
    maskout[j] = a;
}

// ---------------- bilinear align_corners 96 -> 48 ---------------------------
__global__ void k_x1(const float* __restrict__ mask) {
    int k = blockIdx.x * blockDim.x + threadIdx.x;
    if (k >= HW48) return;
    int yo = k / 48, xo = k % 48;
    const float step = 95.f / 47.f;
    float ys = yo * step, xs = xo * step;
    int y0 = (int)floorf(ys), x0 = (int)floorf(xs);
    int y1 = min(y0 + 1, 95), x1i = min(x0 + 1, 95);
    float wy = ys - (float)y0, wx = xs - (float)x0;
    float a = mask[y0 * 96 + x0],  b = mask[y0 * 96 + x1i];
    float c = mask[y1 * 96 + x0],  d = mask[y1 * 96 + x1i];
    g_x1[k] = (a * (1.f - wx) + b * wx) * (1.f - wy) + (c * (1.f - wx) + d * wx) * wy;
}

__global__ void k_attn(const float* __restrict__ A) {
    __shared__ float red[256];
    int j = blockIdx.x;
    int t = threadIdx.x;
    float acc = 0.f;
    const float* row = A + (size_t)j * HW48;
    for (int k = t; k < HW48; k += 256) acc += g_x1[k] * row[k];
    red[t] = acc;
    __syncthreads();
    for (int s = 128; s; s >>= 1) {
        if (t < s) red[t] += red[t + s];
        __syncthreads();
    }
    if (t == 0) g_out48[j] = red[0];
}

__global__ void k_trimap(float* __restrict__ out) {
    int idx = blockIdx.x * blockDim.x + threadIdx.x;
    if (idx >= 768 * 768) return;
    int ox = idx % 768, oy = idx / 768;
    float sx = (ox + 0.5f) * (1.f / 16.f) - 0.5f;
    float sy = (oy + 0.5f) * (1.f / 16.f) - 0.5f;
    int x0 = (int)floorf(sx), y0 = (int)floorf(sy);
    float wx = sx - (float)x0, wy = sy - (float)y0;
    int x0c = max(x0, 0), x1c = min(x0 + 1, 47);
    int y0c = max(y0, 0), y1c = min(y0 + 1, 47);
    float a = g_out48[y0c * 48 + x0c], b = g_out48[y0c * 48 + x1c];
    float c = g_out48[y1c * 48 + x0c], d = g_out48[y1c * 48 + x1c];
    out[idx] = (a * (1.f - wx) + b * wx) * (1.f - wy) + (c * (1.f - wx) + d * wx) * wy;
}

// ---------------- launch ----------------------------------------------------
extern "C" void kernel_launch(void* const* d_in, const int* in_sizes, int n_in,
                              void* d_out, int out_size) {
    (void)in_sizes; (void)n_in; (void)out_size;
    const float* ref_img = (const float*)d_in[0];
    const float* ft_cor  = (const float*)d_in[1];
    const float* attnA   = (const float*)d_in[2];
    const float* ft_mat  = (const float*)d_in[3];
    const float* guid    = (const float*)d_in[4];

    float* out     = (float*)d_out;
    float* trimap  = out;                       // 768*768
    float* matting = out + 768 * 768;           // 1280*64*64
    float* maskout = matting + 1280 * 64 * 64;  // 9216

    k_flag<<<36, 256>>>(guid);
    k_compact<<<1, 256>>>();
    k_weights<<<1, 96>>>();

    k_resize_h2<<<dim3(CDIM * 64 / 16, 1, 2), 256>>>(ft_cor, ref_img);
    k_resize_vt2<<<dim3(NA / 32, CDIM / 32, 2), dim3(32, 8)>>>();

    const int GEMM_SMEM = 3 * 128 * SROWB * 2;   // 61440
    cudaFuncSetAttribute(k_gemm, cudaFuncAttributeMaxDynamicSharedMemorySize,
                         GEMM_SMEM);
    k_gemm<<<dim3(MT, MT), 256, GEMM_SMEM>>>();

    k_invz<<<36, 256>>>();
    k_colreduce<<<dim3(18, SSPLIT), 256>>>();
    k_colfinish<<<36, 256>>>(maskout);

    k_x1<<<9, 256>>>(maskout);
    k_attn<<<HW48, 256>>>(attnA);
    k_trimap<<<(768 * 768 + 255) / 256, 256>>>(trimap);

    cudaMemcpyAsync(matting, ft_mat, (size_t)1280 * 64 * 64 * sizeof(float),
                    cudaMemcpyDeviceToDevice);
}